// round 3
// baseline (speedup 1.0000x reference)
#include <cuda_runtime.h>
#include <cuda_fp16.h>
#include <cstdint>

// ---------------- SMEM layout (bytes) ----------------
#define SM_BIAS   0                   // 256 floats
#define SM_BPROJ  1024                // 12 floats (pad to 1152)
#define SM_A      1152                // 128 rows x 592B (296 halves) = 75776
#define A_STRIDE  592
#define SM_W0     76928               // W chunk buf0: 53248
#define SM_W1     130176              // W chunk buf1: 53248
#define SM_WP     183424              // W_proj: 32 x 528B = 16896
#define SM_TOTAL  200320

#define WC_U4   3328                  // uint4 per W chunk (256 rows x 208B)
#define WP_U4   1056                  // uint4 for W_proj image

// Pre-converted fp16 weight images (static device scratch — no allocation)
__device__ uint4 g_wc[3 * WC_U4];     // 3 K-chunks: [n 0..255][kl 0..103] halves, 208B rows
__device__ uint4 g_wp[WP_U4];         // [n 0..31][k 0..263] halves, 528B rows

static __device__ __forceinline__ uint32_t smem_u32(const void* p) {
    uint32_t r;
    asm("{ .reg .u64 t; cvta.to.shared.u64 t, %1; cvt.u32.u64 %0, t; }" : "=r"(r) : "l"(p));
    return r;
}
static __device__ __forceinline__ uint32_t pack2(float a, float b) {
    __half2 h = __floats2half2_rn(a, b);
    return *reinterpret_cast<uint32_t*>(&h);
}
static __device__ __forceinline__ void cp16(uint32_t dst, const void* src) {
    asm volatile("cp.async.cg.shared.global [%0], [%1], 16;" :: "r"(dst), "l"(src));
}
#define CP_COMMIT()  asm volatile("cp.async.commit_group;" ::: "memory")
#define CP_WAIT(n)   asm volatile("cp.async.wait_group %0;" :: "n"(n) : "memory")

static __device__ __forceinline__ void lds32(uint32_t& v, uint32_t a) {
    asm volatile("ld.shared.b32 %0, [%1];" : "=r"(v) : "r"(a));
}
static __device__ __forceinline__ void sts32(uint32_t a, uint32_t v) {
    asm volatile("st.shared.b32 [%0], %1;" :: "r"(a), "r"(v));
}
static __device__ __forceinline__ void sts64(uint32_t a, uint32_t v0, uint32_t v1) {
    asm volatile("st.shared.v2.b32 [%0], {%1,%2};" :: "r"(a), "r"(v0), "r"(v1));
}
static __device__ __forceinline__ void sts128z(uint32_t a) {
    asm volatile("st.shared.v4.b32 [%0], {%1,%1,%1,%1};" :: "r"(a), "r"(0u));
}
static __device__ __forceinline__ void ldmatrix4(uint32_t& a0, uint32_t& a1,
                                                 uint32_t& a2, uint32_t& a3, uint32_t addr) {
    asm volatile("ldmatrix.sync.aligned.m8n8.x4.shared.b16 {%0,%1,%2,%3}, [%4];"
                 : "=r"(a0), "=r"(a1), "=r"(a2), "=r"(a3) : "r"(addr));
}
#define MMA16816(c0, c1, c2, c3, a0, a1, a2, a3, b0, b1)                          \
    asm volatile("mma.sync.aligned.m16n8k16.row.col.f32.f16.f16.f32 "             \
                 "{%0,%1,%2,%3},{%4,%5,%6,%7},{%8,%9},{%0,%1,%2,%3};"             \
                 : "+f"(c0), "+f"(c1), "+f"(c2), "+f"(c3)                          \
                 : "r"(a0), "r"(a1), "r"(a2), "r"(a3), "r"(b0), "r"(b1))

static __device__ __forceinline__ float tanh_fast(float z) {
    float e = __expf(2.0f * z);                   // MUFU EX2 path (accurate)
    return 1.0f - __fdividef(2.0f, e + 1.0f);     // (e-1)/(e+1)
}

// ================= prep: fp32 -> fp16 weight images =================
// K layout of big GEMM: k 0..255 = W_hh cols, k 256..279 = W_ih cols, 280..287 = 0.
// Split into 3 chunks of K=96 (each row padded to 104 halves = 208B).
__global__ void prep_kernel(const float* __restrict__ W_ih, const float* __restrict__ W_hh,
                            const float* __restrict__ W_proj) {
    int idx = blockIdx.x * 256 + threadIdx.x;
    if (idx < 3 * 256 * 104) {
        int c  = idx / (256 * 104);
        int r  = idx % (256 * 104);
        int n  = r / 104, kl = r % 104;
        int kg = c * 96 + kl;
        float v = 0.0f;
        if (kl < 96) {
            if (kg < 256)      v = W_hh[n * 256 + kg];
            else if (kg < 280) v = W_ih[n * 24 + (kg - 256)];
        }
        reinterpret_cast<__half*>(g_wc)[idx] = __float2half_rn(v);
    } else if (idx < 3 * 256 * 104 + 32 * 264) {
        int r = idx - 3 * 256 * 104;
        int n = r / 264, k = r % 264;
        float v = (n < 12 && k < 256) ? W_proj[n * 256 + k] : 0.0f;
        reinterpret_cast<__half*>(g_wp)[r] = __float2half_rn(v);
    }
}

// ================= main fused kernel: 1 CTA = 128 rows =================
__global__ void __launch_bounds__(256, 1)
rnn_kernel(const float* __restrict__ xin, const float* __restrict__ hidden,
           const float* __restrict__ b_ih, const float* __restrict__ b_hh,
           const float* __restrict__ b_proj,
           float* __restrict__ out, float* __restrict__ h_out) {
    extern __shared__ char smem[];
    const uint32_t sb = smem_u32(smem);
    float* sbias  = reinterpret_cast<float*>(smem + SM_BIAS);
    float* sbproj = reinterpret_cast<float*>(smem + SM_BPROJ);

    const int tid  = threadIdx.x;
    const int w    = tid >> 5;
    const int lane = tid & 31;
    const int g    = lane >> 2;        // group 0..7
    const int tg   = lane & 3;         // thread-in-group 0..3
    const size_t rowbase = (size_t)blockIdx.x * 128;

    // ---- issue async weight copies: group0 = wp + chunk0, group1 = chunk1 ----
    {
        const uint4* src = g_wp;
#pragma unroll
        for (int it = 0; it < 5; it++) {
            int i = tid + it * 256;
            if (i < WP_U4) cp16(sb + SM_WP + i * 16, src + i);
        }
#pragma unroll
        for (int it = 0; it < 13; it++) {
            int i = tid + it * 256;
            cp16(sb + SM_W0 + i * 16, g_wc + i);
        }
        CP_COMMIT();
#pragma unroll
        for (int it = 0; it < 13; it++) {
            int i = tid + it * 256;
            cp16(sb + SM_W1 + i * 16, g_wc + WC_U4 + i);
        }
        CP_COMMIT();
    }

    // ---- A fill: hidden (fp32 -> fp16) ----
    {
        const float4* hsrc = (const float4*)(hidden + rowbase * 256);
#pragma unroll
        for (int it = 0; it < 32; it++) {
            int j = tid + it * 256;               // 0..8191
            int row = j >> 6, c4 = j & 63;
            float4 f = hsrc[j];
            sts64(sb + SM_A + row * A_STRIDE + c4 * 8, pack2(f.x, f.y), pack2(f.z, f.w));
        }
        const float2* xsrc = (const float2*)(xin + rowbase * 24);
#pragma unroll
        for (int it = 0; it < 6; it++) {
            int j = tid + it * 256;               // 0..1535
            int row = j / 12, c2 = j % 12;
            float2 f = xsrc[j];
            sts32(sb + SM_A + row * A_STRIDE + 512 + c2 * 4, pack2(f.x, f.y));
        }
        if (tid < 128) sts128z(sb + SM_A + tid * A_STRIDE + 560);   // zero k 280..287
        sbias[tid] = b_ih[tid] + b_hh[tid];
        if (tid < 12) sbproj[tid] = b_proj[tid];
    }

    CP_WAIT(1);          // wp + chunk0 resident
    __syncthreads();     // + A resident

    // ---- MMA1: [128 x 288] x [288 x 256]^T, N-split across 8 warps ----
    float acc[128];
#pragma unroll
    for (int i = 0; i < 128; i++) acc[i] = 0.0f;

    const uint32_t abase = sb + SM_A + (lane & 15) * A_STRIDE + (lane >> 4) * 16;
    const int nb = w * 32;

#pragma unroll
    for (int c = 0; c < 3; c++) {
        const uint32_t wb = sb + ((c == 1) ? SM_W1 : SM_W0);
#pragma unroll
        for (int kl = 0; kl < 6; kl++) {
            const int ks = c * 6 + kl;
            uint32_t b[4][2];
#pragma unroll
            for (int nt = 0; nt < 4; nt++) {
                uint32_t ba = wb + (uint32_t)(nb + nt * 8 + g) * 208 + kl * 32 + tg * 4;
                lds32(b[nt][0], ba);
                lds32(b[nt][1], ba + 16);
            }
#pragma unroll
            for (int mt = 0; mt < 8; mt++) {
                uint32_t a0, a1, a2, a3;
                ldmatrix4(a0, a1, a2, a3, abase + mt * (16 * A_STRIDE) + ks * 32);
#pragma unroll
                for (int nt = 0; nt < 4; nt++) {
                    const int i = (mt * 4 + nt) * 4;
                    MMA16816(acc[i], acc[i + 1], acc[i + 2], acc[i + 3],
                             a0, a1, a2, a3, b[nt][0], b[nt][1]);
                }
            }
        }
        if (c == 0) {
            __syncthreads();                       // everyone done reading W0
#pragma unroll
            for (int it = 0; it < 13; it++) {      // chunk2 -> buf0
                int i = tid + it * 256;
                cp16(sb + SM_W0 + i * 16, g_wc + 2 * WC_U4 + i);
            }
            CP_COMMIT();
            CP_WAIT(1);                            // chunk1 resident
            __syncthreads();
        } else if (c == 1) {
            CP_WAIT(0);                            // chunk2 resident
            __syncthreads();
        }
    }

    // ---- epilogue 1: bias + tanh, STG h_new ----
#pragma unroll
    for (int mt = 0; mt < 8; mt++) {
#pragma unroll
        for (int nt = 0; nt < 4; nt++) {
            const int n = nb + nt * 8 + tg * 2;
            const float bb0 = sbias[n], bb1 = sbias[n + 1];
            const int i = (mt * 4 + nt) * 4;
            acc[i + 0] = tanh_fast(acc[i + 0] + bb0);
            acc[i + 1] = tanh_fast(acc[i + 1] + bb1);
            acc[i + 2] = tanh_fast(acc[i + 2] + bb0);
            acc[i + 3] = tanh_fast(acc[i + 3] + bb1);
            const int m0 = mt * 16 + g;
            *(float2*)(h_out + (rowbase + m0) * 256 + n)     = make_float2(acc[i], acc[i + 1]);
            *(float2*)(h_out + (rowbase + m0 + 8) * 256 + n) = make_float2(acc[i + 2], acc[i + 3]);
        }
    }
    __syncthreads();     // all warps done reading A (MMA1 complete)

    // ---- repack h_new fp16 into A region (k 0..255) ----
#pragma unroll
    for (int mt = 0; mt < 8; mt++) {
#pragma unroll
        for (int nt = 0; nt < 4; nt++) {
            const int n = nb + nt * 8 + tg * 2;
            const int i = (mt * 4 + nt) * 4;
            const int m0 = mt * 16 + g;
            sts32(sb + SM_A + m0 * A_STRIDE + n * 2,       pack2(acc[i], acc[i + 1]));
            sts32(sb + SM_A + (m0 + 8) * A_STRIDE + n * 2, pack2(acc[i + 2], acc[i + 3]));
        }
    }
    __syncthreads();

    // ---- MMA2: logits = h_new x W_proj^T  (warp w owns rows w*16..w*16+15) ----
    float pa[16];
#pragma unroll
    for (int i = 0; i < 16; i++) pa[i] = 0.0f;
    const uint32_t a2base = sb + SM_A + (w * 16 + (lane & 15)) * A_STRIDE + (lane >> 4) * 16;
#pragma unroll
    for (int ks = 0; ks < 16; ks++) {
        uint32_t a0, a1, a2, a3;
        ldmatrix4(a0, a1, a2, a3, a2base + ks * 32);
#pragma unroll
        for (int nt = 0; nt < 4; nt++) {
            uint32_t b0, b1;
            uint32_t ba = sb + SM_WP + (uint32_t)(nt * 8 + g) * 528 + ks * 32 + tg * 4;
            lds32(b0, ba);
            lds32(b1, ba + 16);
            MMA16816(pa[nt * 4], pa[nt * 4 + 1], pa[nt * 4 + 2], pa[nt * 4 + 3],
                     a0, a1, a2, a3, b0, b1);
        }
    }

    // ---- epilogue 2: softmax over 12 logits (quad reduction) ----
    {
        const int m0 = w * 16 + g;
        float l0[4], l1[4];   // per row: n = 2tg, 2tg+1, 8+2tg, 9+2tg
        const int na = tg * 2, nb2 = 8 + tg * 2;
        const bool v1 = (nb2 < 12);
        l0[0] = pa[0] + sbproj[na];  l0[1] = pa[1] + sbproj[na + 1];
        l1[0] = pa[2] + sbproj[na];  l1[1] = pa[3] + sbproj[na + 1];
        l0[2] = v1 ? pa[4] + sbproj[nb2]     : -1e30f;
        l0[3] = v1 ? pa[5] + sbproj[nb2 + 1] : -1e30f;
        l1[2] = v1 ? pa[6] + sbproj[nb2]     : -1e30f;
        l1[3] = v1 ? pa[7] + sbproj[nb2 + 1] : -1e30f;

        float mx0 = fmaxf(fmaxf(l0[0], l0[1]), fmaxf(l0[2], l0[3]));
        float mx1 = fmaxf(fmaxf(l1[0], l1[1]), fmaxf(l1[2], l1[3]));
        mx0 = fmaxf(mx0, __shfl_xor_sync(0xFFFFFFFFu, mx0, 1));
        mx0 = fmaxf(mx0, __shfl_xor_sync(0xFFFFFFFFu, mx0, 2));
        mx1 = fmaxf(mx1, __shfl_xor_sync(0xFFFFFFFFu, mx1, 1));
        mx1 = fmaxf(mx1, __shfl_xor_sync(0xFFFFFFFFu, mx1, 2));

        float s0 = 0.f, s1 = 0.f;
#pragma unroll
        for (int j = 0; j < 4; j++) { l0[j] = __expf(l0[j] - mx0); s0 += l0[j]; }
#pragma unroll
        for (int j = 0; j < 4; j++) { l1[j] = __expf(l1[j] - mx1); s1 += l1[j]; }
        s0 += __shfl_xor_sync(0xFFFFFFFFu, s0, 1);
        s0 += __shfl_xor_sync(0xFFFFFFFFu, s0, 2);
        s1 += __shfl_xor_sync(0xFFFFFFFFu, s1, 1);
        s1 += __shfl_xor_sync(0xFFFFFFFFu, s1, 2);
        const float i0 = __fdividef(1.0f, s0);
        const float i1 = __fdividef(1.0f, s1);

        float* o0 = out + (rowbase + m0) * 12;
        float* o1 = out + (rowbase + m0 + 8) * 12;
        *(float2*)(o0 + na) = make_float2(l0[0] * i0, l0[1] * i0);
        *(float2*)(o1 + na) = make_float2(l1[0] * i1, l1[1] * i1);
        if (v1) {
            *(float2*)(o0 + nb2) = make_float2(l0[2] * i0, l0[3] * i0);
            *(float2*)(o1 + nb2) = make_float2(l1[2] * i1, l1[3] * i1);
        }
    }
}

extern "C" void kernel_launch(void* const* d_in, const int* in_sizes, int n_in,
                              void* d_out, int out_size) {
    const float* x      = (const float*)d_in[0];
    const float* hidden = (const float*)d_in[1];
    const float* W_ih   = (const float*)d_in[2];
    const float* b_ih   = (const float*)d_in[3];
    const float* W_hh   = (const float*)d_in[4];
    const float* b_hh   = (const float*)d_in[5];
    const float* W_proj = (const float*)d_in[6];
    const float* b_proj = (const float*)d_in[7];

    const int N = in_sizes[0] / 24;            // 524288
    float* out   = (float*)d_out;              // [N,12] softmax
    float* h_out = out + (size_t)N * 12;       // [N,256] h_new

    cudaFuncSetAttribute(rnn_kernel, cudaFuncAttributeMaxDynamicSharedMemorySize, SM_TOTAL);

    prep_kernel<<<345, 256>>>(W_ih, W_hh, W_proj);
    rnn_kernel<<<N / 128, 256, SM_TOTAL>>>(x, hidden, b_ih, b_hh, b_proj, out, h_out);
}

// round 5
// speedup vs baseline: 1.2053x; 1.2053x over previous
#include <cuda_runtime.h>
#include <cuda_fp16.h>
#include <cstdint>

// ---------------- SMEM layout (bytes) ----------------
#define SM_BIAS   0                    // 256 floats
#define SM_BPROJ  1024                 // 16 floats
#define SM_W      1152                 // W image: 256 rows x 592B = 151552
#define W_STRIDE  592                  // 296 halves (288 used + pad), conflict-free ldmatrix
#define SM_WP     (1152 + 151552)      // 152704: W_proj 32 rows x 528B = 16896
#define WP_STRIDE 528
#define SM_TOTAL  (152704 + 16896)     // 169600

#define W_U4   9472                    // 151552 / 16
#define WP_U4  1056                    // 16896 / 16

// Pre-converted fp16 weight images (static device scratch — no allocation)
__device__ uint4 g_w[W_U4];            // [n 0..255][k 0..295 halves]; k<256=W_hh, 256..279=W_ih, pad 0
__device__ uint4 g_wp[WP_U4];          // [n 0..31][k 0..263 halves]; n<12,k<256=W_proj else 0

static __device__ __forceinline__ uint32_t smem_u32(const void* p) {
    uint32_t r;
    asm("{ .reg .u64 t; cvta.to.shared.u64 t, %1; cvt.u32.u64 %0, t; }" : "=r"(r) : "l"(p));
    return r;
}
static __device__ __forceinline__ uint32_t pack2(float a, float b) {
    __half2 h = __floats2half2_rn(a, b);
    return *reinterpret_cast<uint32_t*>(&h);
}
static __device__ __forceinline__ void cp16(uint32_t dst, const void* src) {
    asm volatile("cp.async.cg.shared.global [%0], [%1], 16;" :: "r"(dst), "l"(src));
}
#define CP_COMMIT()  asm volatile("cp.async.commit_group;" ::: "memory")
#define CP_WAIT(n)   asm volatile("cp.async.wait_group %0;" :: "n"(n) : "memory")

static __device__ __forceinline__ void lds32(uint32_t& v, uint32_t a) {
    asm volatile("ld.shared.b32 %0, [%1];" : "=r"(v) : "r"(a));
}
static __device__ __forceinline__ void ldmatrix4(uint32_t& a0, uint32_t& a1,
                                                 uint32_t& a2, uint32_t& a3, uint32_t addr) {
    asm volatile("ldmatrix.sync.aligned.m8n8.x4.shared.b16 {%0,%1,%2,%3}, [%4];"
                 : "=r"(a0), "=r"(a1), "=r"(a2), "=r"(a3) : "r"(addr));
}
#define MMA16816(c0, c1, c2, c3, a0, a1, a2, a3, b0, b1)                          \
    asm volatile("mma.sync.aligned.m16n8k16.row.col.f32.f16.f16.f32 "             \
                 "{%0,%1,%2,%3},{%4,%5,%6,%7},{%8,%9},{%0,%1,%2,%3};"             \
                 : "+f"(c0), "+f"(c1), "+f"(c2), "+f"(c3)                          \
                 : "r"(a0), "r"(a1), "r"(a2), "r"(a3), "r"(b0), "r"(b1))

static __device__ __forceinline__ float tanh_fast(float z) {
    float e = __expf(2.0f * z);                   // MUFU EX2 path (accurate)
    return 1.0f - __fdividef(2.0f, e + 1.0f);     // (e-1)/(e+1)
}

// ================= prep: fp32 -> fp16 padded weight images =================
__global__ void prep_kernel(const float* __restrict__ W_ih, const float* __restrict__ W_hh,
                            const float* __restrict__ W_proj) {
    int idx = blockIdx.x * 256 + threadIdx.x;
    if (idx < 256 * 296) {
        int n = idx / 296, k = idx % 296;
        float v = 0.0f;
        if (k < 256)      v = W_hh[n * 256 + k];
        else if (k < 280) v = W_ih[n * 24 + (k - 256)];
        reinterpret_cast<__half*>(g_w)[idx] = __float2half_rn(v);
    } else {
        int r = idx - 256 * 296;          // 0 .. 8447
        int n = r / 264, k = r % 264;
        float v = (n < 12 && k < 256) ? W_proj[n * 256 + k] : 0.0f;
        reinterpret_cast<__half*>(g_wp)[r] = __float2half_rn(v);
    }
}

// ================= persistent fused kernel: 1 warp = 16 rows, no in-loop syncs =================
__global__ void __launch_bounds__(256, 1)
rnn_kernel(const float* __restrict__ xin, const float* __restrict__ hidden,
           const float* __restrict__ b_ih, const float* __restrict__ b_hh,
           const float* __restrict__ b_proj,
           float* __restrict__ out, float* __restrict__ h_out, int ntiles) {
    extern __shared__ char smem[];
    const uint32_t sb = smem_u32(smem);
    float* sbias  = reinterpret_cast<float*>(smem + SM_BIAS);
    float* sbproj = reinterpret_cast<float*>(smem + SM_BPROJ);

    const int tid  = threadIdx.x;
    const int w    = tid >> 5;
    const int lane = tid & 31;
    const int g    = lane >> 2;         // fragment row group 0..7
    const int c0   = (lane & 3) * 2;    // fragment col base 0,2,4,6

    // ---- resident W load (once per CTA) ----
#pragma unroll
    for (int it = 0; it < 37; it++) {
        int i = tid + it * 256;
        cp16(sb + SM_W + i * 16, g_w + i);
    }
#pragma unroll
    for (int it = 0; it < 5; it++) {
        int i = tid + it * 256;
        if (i < WP_U4) cp16(sb + SM_WP + i * 16, g_wp + i);
    }
    CP_COMMIT();
    sbias[tid] = b_ih[tid] + b_hh[tid];
    if (tid < 16) sbproj[tid] = (tid < 12) ? b_proj[tid] : 0.0f;
    CP_WAIT(0);
    __syncthreads();

    // ---- ldmatrix B base: matrix m = lane>>3 covers nt-parity (m>>1), k-half (m&1);
    //      quad q adds 16 rows (2 n-tiles) = q*16*W_STRIDE bytes ----
    const int mrole = lane >> 3, mrow = lane & 7;
    const uint32_t wq0 = sb + SM_W +
        (uint32_t)(((mrole >> 1) * 8 + mrow) * W_STRIDE) + (mrole & 1) * 16;
    const uint32_t pb0 = sb + SM_WP + (uint32_t)(g * WP_STRIDE) + (lane & 3) * 4;
    const uint32_t pb1 = pb0 + 8 * WP_STRIDE;

    const int nwarp = gridDim.x * 8;
    for (int t = blockIdx.x * 8 + w; t < ntiles; t += nwarp) {
        const size_t r0 = (size_t)t * 16 + g;
        const float* h0 = hidden + r0 * 256;
        const float* h8 = h0 + 8 * 256;
        const float* x0 = xin + r0 * 24;
        const float* x8 = x0 + 8 * 24;

        // ---- acc init = bias (folds epilogue add) ----
        float acc[128];
#pragma unroll
        for (int nt = 0; nt < 32; nt++) {
            float2 bb = *(const float2*)(sbias + nt * 8 + c0);
            acc[4 * nt + 0] = bb.x; acc[4 * nt + 1] = bb.y;
            acc[4 * nt + 2] = bb.x; acc[4 * nt + 3] = bb.y;
        }

        // ---- MMA1: 16 rows x 256 N x K=288, A from global, 1-step prefetch ----
        float2 s[2][4];
        s[0][0] = *(const float2*)(h0 + c0);
        s[0][1] = *(const float2*)(h8 + c0);
        s[0][2] = *(const float2*)(h0 + 8 + c0);
        s[0][3] = *(const float2*)(h8 + 8 + c0);

#pragma unroll
        for (int ks = 0; ks < 18; ks++) {
            const int cur = ks & 1, nxt = cur ^ 1;
            const int kn = ks + 1;
            if (kn < 16) {
                s[nxt][0] = *(const float2*)(h0 + kn * 16 + c0);
                s[nxt][1] = *(const float2*)(h8 + kn * 16 + c0);
                s[nxt][2] = *(const float2*)(h0 + kn * 16 + 8 + c0);
                s[nxt][3] = *(const float2*)(h8 + kn * 16 + 8 + c0);
            } else if (kn == 16) {
                s[nxt][0] = *(const float2*)(x0 + c0);
                s[nxt][1] = *(const float2*)(x8 + c0);
                s[nxt][2] = *(const float2*)(x0 + 8 + c0);
                s[nxt][3] = *(const float2*)(x8 + 8 + c0);
            } else if (kn == 17) {
                s[nxt][0] = *(const float2*)(x0 + 16 + c0);
                s[nxt][1] = *(const float2*)(x8 + 16 + c0);
                s[nxt][2] = make_float2(0.f, 0.f);
                s[nxt][3] = make_float2(0.f, 0.f);
            }
            const uint32_t a0 = pack2(s[cur][0].x, s[cur][0].y);
            const uint32_t a1 = pack2(s[cur][1].x, s[cur][1].y);
            const uint32_t a2 = pack2(s[cur][2].x, s[cur][2].y);
            const uint32_t a3 = pack2(s[cur][3].x, s[cur][3].y);
#pragma unroll
            for (int q = 0; q < 16; q++) {            // FIX: full 32 n-tiles (was 8 -> cols 0..127 only)
                uint32_t b0, b1, b2, b3;
                ldmatrix4(b0, b1, b2, b3,
                          wq0 + (uint32_t)q * (16 * W_STRIDE) + ks * 32);
                const int i = q * 8;
                MMA16816(acc[i + 0], acc[i + 1], acc[i + 2], acc[i + 3],
                         a0, a1, a2, a3, b0, b1);
                MMA16816(acc[i + 4], acc[i + 5], acc[i + 6], acc[i + 7],
                         a0, a1, a2, a3, b2, b3);
            }
        }

        // ---- tanh + store h_new ----
#pragma unroll
        for (int i = 0; i < 128; i++) acc[i] = tanh_fast(acc[i]);

        float* ho0 = h_out + r0 * 256;
        float* ho8 = ho0 + 8 * 256;
#pragma unroll
        for (int nt = 0; nt < 32; nt++) {
            *(float2*)(ho0 + nt * 8 + c0) = make_float2(acc[4 * nt + 0], acc[4 * nt + 1]);
            *(float2*)(ho8 + nt * 8 + c0) = make_float2(acc[4 * nt + 2], acc[4 * nt + 3]);
        }

        // ---- proj: logits cols 0..15 (12 used); A frags straight from acc regs ----
        float pa[8];
        {
            float2 q0 = *(const float2*)(sbproj + c0);
            float2 q1 = *(const float2*)(sbproj + 8 + c0);
            pa[0] = q0.x; pa[1] = q0.y; pa[2] = q0.x; pa[3] = q0.y;
            pa[4] = q1.x; pa[5] = q1.y; pa[6] = q1.x; pa[7] = q1.y;
        }
#pragma unroll
        for (int ks = 0; ks < 16; ks++) {
            const uint32_t a0 = pack2(acc[8 * ks + 0], acc[8 * ks + 1]);
            const uint32_t a1 = pack2(acc[8 * ks + 2], acc[8 * ks + 3]);
            const uint32_t a2 = pack2(acc[8 * ks + 4], acc[8 * ks + 5]);
            const uint32_t a3 = pack2(acc[8 * ks + 6], acc[8 * ks + 7]);
            uint32_t b0, b1;
            lds32(b0, pb0 + ks * 32); lds32(b1, pb0 + ks * 32 + 16);
            MMA16816(pa[0], pa[1], pa[2], pa[3], a0, a1, a2, a3, b0, b1);
            lds32(b0, pb1 + ks * 32); lds32(b1, pb1 + ks * 32 + 16);
            MMA16816(pa[4], pa[5], pa[6], pa[7], a0, a1, a2, a3, b0, b1);
        }

        // ---- softmax over 12 logits (quad reduction) ----
        {
            const bool v1 = (8 + c0) < 12;
            float l0[4], l1[4];
            l0[0] = pa[0]; l0[1] = pa[1]; l1[0] = pa[2]; l1[1] = pa[3];
            l0[2] = v1 ? pa[4] : -1e30f; l0[3] = v1 ? pa[5] : -1e30f;
            l1[2] = v1 ? pa[6] : -1e30f; l1[3] = v1 ? pa[7] : -1e30f;

            float mx0 = fmaxf(fmaxf(l0[0], l0[1]), fmaxf(l0[2], l0[3]));
            float mx1 = fmaxf(fmaxf(l1[0], l1[1]), fmaxf(l1[2], l1[3]));
            mx0 = fmaxf(mx0, __shfl_xor_sync(0xFFFFFFFFu, mx0, 1));
            mx0 = fmaxf(mx0, __shfl_xor_sync(0xFFFFFFFFu, mx0, 2));
            mx1 = fmaxf(mx1, __shfl_xor_sync(0xFFFFFFFFu, mx1, 1));
            mx1 = fmaxf(mx1, __shfl_xor_sync(0xFFFFFFFFu, mx1, 2));

            float s0 = 0.f, s1 = 0.f;
#pragma unroll
            for (int j = 0; j < 4; j++) { l0[j] = __expf(l0[j] - mx0); s0 += l0[j]; }
#pragma unroll
            for (int j = 0; j < 4; j++) { l1[j] = __expf(l1[j] - mx1); s1 += l1[j]; }
            s0 += __shfl_xor_sync(0xFFFFFFFFu, s0, 1);
            s0 += __shfl_xor_sync(0xFFFFFFFFu, s0, 2);
            s1 += __shfl_xor_sync(0xFFFFFFFFu, s1, 1);
            s1 += __shfl_xor_sync(0xFFFFFFFFu, s1, 2);
            const float i0 = __fdividef(1.0f, s0);
            const float i1 = __fdividef(1.0f, s1);

            float* o0 = out + r0 * 12;
            float* o1 = out + (r0 + 8) * 12;
            *(float2*)(o0 + c0) = make_float2(l0[0] * i0, l0[1] * i0);
            *(float2*)(o1 + c0) = make_float2(l1[0] * i1, l1[1] * i1);
            if (v1) {
                *(float2*)(o0 + 8 + c0) = make_float2(l0[2] * i0, l0[3] * i0);
                *(float2*)(o1 + 8 + c0) = make_float2(l1[2] * i1, l1[3] * i1);
            }
        }
    }
}

extern "C" void kernel_launch(void* const* d_in, const int* in_sizes, int n_in,
                              void* d_out, int out_size) {
    const float* x      = (const float*)d_in[0];
    const float* hidden = (const float*)d_in[1];
    const float* W_ih   = (const float*)d_in[2];
    const float* b_ih   = (const float*)d_in[3];
    const float* W_hh   = (const float*)d_in[4];
    const float* b_hh   = (const float*)d_in[5];
    const float* W_proj = (const float*)d_in[6];
    const float* b_proj = (const float*)d_in[7];

    const int N = in_sizes[0] / 24;            // 524288
    float* out   = (float*)d_out;              // [N,12] softmax
    float* h_out = out + (size_t)N * 12;       // [N,256] h_new

    cudaFuncSetAttribute(rnn_kernel, cudaFuncAttributeMaxDynamicSharedMemorySize, SM_TOTAL);

    prep_kernel<<<329, 256>>>(W_ih, W_hh, W_proj);               // 84224 threads exactly
    rnn_kernel<<<152, 256, SM_TOTAL>>>(x, hidden, b_ih, b_hh, b_proj,
                                       out, h_out, N / 16);      // persistent, GB300 = 152 SMs
}

// round 6
// speedup vs baseline: 1.2384x; 1.0275x over previous
#include <cuda_runtime.h>
#include <cuda_fp16.h>
#include <cstdint>

// ---------------- SMEM layout (bytes) ----------------
#define SM_BIAS   0                    // 256 floats
#define SM_BPROJ  1024                 // 16 floats
#define SM_W      1152                 // W image: 256 rows x 592B = 151552
#define W_STRIDE  592                  // 296 halves (288 used + pad), conflict-free ldmatrix
#define SM_WP     (1152 + 151552)      // 152704: W_proj 32 rows x 528B = 16896
#define WP_STRIDE 528
#define SM_SCR    (152704 + 16896)     // 169600: proj partial scratch, 4 pairs x 4608B
#define SCR_PAIR  4608                 // 2 halves x 32 rows x 72B (18-float row stride)
#define SM_TOTAL  (169600 + 4 * 4608)  // 188032

#define W_U4   9472                    // 151552 / 16
#define WP_U4  1056                    // 16896 / 16

// Pre-converted fp16 weight images (static device scratch — no allocation)
__device__ uint4 g_w[W_U4];            // [n 0..255][k 0..295 halves]; k<256=W_hh, 256..279=W_ih, pad 0
__device__ uint4 g_wp[WP_U4];          // [n 0..31][k 0..263 halves]; n<12,k<256=W_proj else 0

static __device__ __forceinline__ uint32_t smem_u32(const void* p) {
    uint32_t r;
    asm("{ .reg .u64 t; cvta.to.shared.u64 t, %1; cvt.u32.u64 %0, t; }" : "=r"(r) : "l"(p));
    return r;
}
static __device__ __forceinline__ uint32_t pack2(float a, float b) {
    __half2 h = __floats2half2_rn(a, b);
    return *reinterpret_cast<uint32_t*>(&h);
}
static __device__ __forceinline__ void cp16(uint32_t dst, const void* src) {
    asm volatile("cp.async.cg.shared.global [%0], [%1], 16;" :: "r"(dst), "l"(src));
}
#define CP_COMMIT()  asm volatile("cp.async.commit_group;" ::: "memory")
#define CP_WAIT(n)   asm volatile("cp.async.wait_group %0;" :: "n"(n) : "memory")

static __device__ __forceinline__ void lds32(uint32_t& v, uint32_t a) {
    asm volatile("ld.shared.b32 %0, [%1];" : "=r"(v) : "r"(a));
}
static __device__ __forceinline__ void ldsf2(float& v0, float& v1, uint32_t a) {
    asm volatile("ld.shared.v2.f32 {%0,%1}, [%2];" : "=f"(v0), "=f"(v1) : "r"(a));
}
static __device__ __forceinline__ void stsf2(uint32_t a, float v0, float v1) {
    asm volatile("st.shared.v2.f32 [%0], {%1,%2};" :: "r"(a), "f"(v0), "f"(v1));
}
static __device__ __forceinline__ void ldmatrix4(uint32_t& a0, uint32_t& a1,
                                                 uint32_t& a2, uint32_t& a3, uint32_t addr) {
    asm volatile("ldmatrix.sync.aligned.m8n8.x4.shared.b16 {%0,%1,%2,%3}, [%4];"
                 : "=r"(a0), "=r"(a1), "=r"(a2), "=r"(a3) : "r"(addr));
}
#define MMA16816(c0, c1, c2, c3, a0, a1, a2, a3, b0, b1)                          \
    asm volatile("mma.sync.aligned.m16n8k16.row.col.f32.f16.f16.f32 "             \
                 "{%0,%1,%2,%3},{%4,%5,%6,%7},{%8,%9},{%0,%1,%2,%3};"             \
                 : "+f"(c0), "+f"(c1), "+f"(c2), "+f"(c3)                          \
                 : "r"(a0), "r"(a1), "r"(a2), "r"(a3), "r"(b0), "r"(b1))
#define BAR_PAIR(id) asm volatile("bar.sync %0, 64;" :: "r"(id) : "memory")

static __device__ __forceinline__ float tanh_fast(float z) {
    float e = __expf(2.0f * z);                   // MUFU EX2 path (accurate)
    return 1.0f - __fdividef(2.0f, e + 1.0f);     // (e-1)/(e+1)
}

// ================= prep: fp32 -> fp16 padded weight images =================
__global__ void prep_kernel(const float* __restrict__ W_ih, const float* __restrict__ W_hh,
                            const float* __restrict__ W_proj) {
    int idx = blockIdx.x * 256 + threadIdx.x;
    if (idx < 256 * 296) {
        int n = idx / 296, k = idx % 296;
        float v = 0.0f;
        if (k < 256)      v = W_hh[n * 256 + k];
        else if (k < 280) v = W_ih[n * 24 + (k - 256)];
        reinterpret_cast<__half*>(g_w)[idx] = __float2half_rn(v);
    } else {
        int r = idx - 256 * 296;          // 0 .. 8447
        int n = r / 264, k = r % 264;
        float v = (n < 12 && k < 256) ? W_proj[n * 256 + k] : 0.0f;
        reinterpret_cast<__half*>(g_wp)[r] = __float2half_rn(v);
    }
}

// ====== persistent fused kernel: warp = 32 rows x 128 cols; warp pairs split N ======
__global__ void __launch_bounds__(256, 1)
rnn_kernel(const float* __restrict__ xin, const float* __restrict__ hidden,
           const float* __restrict__ b_ih, const float* __restrict__ b_hh,
           const float* __restrict__ b_proj,
           float* __restrict__ out, float* __restrict__ h_out, int ntiles) {
    extern __shared__ char smem[];
    const uint32_t sb = smem_u32(smem);
    float* sbias  = reinterpret_cast<float*>(smem + SM_BIAS);
    float* sbproj = reinterpret_cast<float*>(smem + SM_BPROJ);

    const int tid  = threadIdx.x;
    const int w    = tid >> 5;
    const int lane = tid & 31;
    const int g    = lane >> 2;          // fragment row group 0..7
    const int c0   = (lane & 3) * 2;     // fragment col base 0,2,4,6
    const int pair = w >> 1;             // 0..3
    const int nh   = w & 1;              // N-half: cols [nh*128, nh*128+128)

    // ---- resident W load (once per CTA) ----
#pragma unroll
    for (int it = 0; it < 37; it++) {
        int i = tid + it * 256;
        cp16(sb + SM_W + i * 16, g_w + i);
    }
#pragma unroll
    for (int it = 0; it < 5; it++) {
        int i = tid + it * 256;
        if (i < WP_U4) cp16(sb + SM_WP + i * 16, g_wp + i);
    }
    CP_COMMIT();
    sbias[tid] = b_ih[tid] + b_hh[tid];
    if (tid < 16) sbproj[tid] = (tid < 12) ? b_proj[tid] : 0.0f;
    CP_WAIT(0);
    __syncthreads();

    // ---- ldmatrix B base (matrix m = lane>>3: nt-parity m>>1, k-half m&1) ----
    const int mrole = lane >> 3, mrow = lane & 7;
    const uint32_t wq0 = sb + SM_W +
        (uint32_t)((nh * 128 + (mrole >> 1) * 8 + mrow) * W_STRIDE) + (mrole & 1) * 16;
    // proj B bases (K-chunk of this half), n-tiles 0 and 1
    const uint32_t pbase = sb + SM_WP + (uint32_t)(nh * 256) + (lane & 3) * 4;
    const uint32_t pb0 = pbase + (uint32_t)(g * WP_STRIDE);
    const uint32_t pb1 = pbase + (uint32_t)((8 + g) * WP_STRIDE);
    // scratch for this pair
    const uint32_t scrW = sb + SM_SCR + pair * SCR_PAIR + nh * 2304;        // my write region
    const uint32_t scrR = sb + SM_SCR + pair * SCR_PAIR + (1 - nh) * 2304;  // partner region
    const int barid = pair + 1;

    const int npair = gridDim.x * 4;
    for (int t = blockIdx.x * 4 + pair; t < ntiles; t += npair) {
        const size_t r0 = (size_t)t * 32;
        const float* hrow = hidden + (r0 + g) * 256;
        const float* xrow = xin + (r0 + g) * 24;

        // ---- acc init = bias ----  i = q*16 + nt*8 + half*4
        float acc[128];
#pragma unroll
        for (int q = 0; q < 8; q++)
#pragma unroll
            for (int nt = 0; nt < 2; nt++) {
                float2 bb = *(const float2*)(sbias + nh * 128 + q * 16 + nt * 8 + c0);
                const int i = q * 16 + nt * 8;
                acc[i + 0] = bb.x; acc[i + 1] = bb.y; acc[i + 2] = bb.x; acc[i + 3] = bb.y;
                acc[i + 4] = bb.x; acc[i + 5] = bb.y; acc[i + 6] = bb.x; acc[i + 7] = bb.y;
            }

        // ---- MMA1: 32 rows x 128 cols x K=288, A from global, 1-step prefetch ----
        // s[buf][0..3] = k-half0 rows g,g+8,g+16,g+24 ; s[buf][4..7] = k-half1 same rows
        float2 s[2][8];
#pragma unroll
        for (int rr = 0; rr < 4; rr++) {
            s[0][rr]     = *(const float2*)(hrow + rr * 8 * 256 + c0);
            s[0][4 + rr] = *(const float2*)(hrow + rr * 8 * 256 + 8 + c0);
        }

#pragma unroll
        for (int ks = 0; ks < 18; ks++) {
            const int cur = ks & 1, nxt = cur ^ 1;
            const int kn = ks + 1;
            if (kn < 16) {
#pragma unroll
                for (int rr = 0; rr < 4; rr++) {
                    s[nxt][rr]     = *(const float2*)(hrow + rr * 8 * 256 + kn * 16 + c0);
                    s[nxt][4 + rr] = *(const float2*)(hrow + rr * 8 * 256 + kn * 16 + 8 + c0);
                }
            } else if (kn == 16) {
#pragma unroll
                for (int rr = 0; rr < 4; rr++) {
                    s[nxt][rr]     = *(const float2*)(xrow + rr * 8 * 24 + c0);
                    s[nxt][4 + rr] = *(const float2*)(xrow + rr * 8 * 24 + 8 + c0);
                }
            } else if (kn == 17) {
#pragma unroll
                for (int rr = 0; rr < 4; rr++) {
                    s[nxt][rr]     = *(const float2*)(xrow + rr * 8 * 24 + 16 + c0);
                    s[nxt][4 + rr] = make_float2(0.f, 0.f);
                }
            }
            const uint32_t a0 = pack2(s[cur][0].x, s[cur][0].y);   // row g,    kh0
            const uint32_t a1 = pack2(s[cur][1].x, s[cur][1].y);   // row g+8,  kh0
            const uint32_t a2 = pack2(s[cur][4].x, s[cur][4].y);   // row g,    kh1
            const uint32_t a3 = pack2(s[cur][5].x, s[cur][5].y);   // row g+8,  kh1
            const uint32_t a4 = pack2(s[cur][2].x, s[cur][2].y);   // row g+16, kh0
            const uint32_t a5 = pack2(s[cur][3].x, s[cur][3].y);   // row g+24, kh0
            const uint32_t a6 = pack2(s[cur][6].x, s[cur][6].y);   // row g+16, kh1
            const uint32_t a7 = pack2(s[cur][7].x, s[cur][7].y);   // row g+24, kh1
#pragma unroll
            for (int q = 0; q < 8; q++) {
                uint32_t b0, b1, b2, b3;
                ldmatrix4(b0, b1, b2, b3,
                          wq0 + (uint32_t)q * (16 * W_STRIDE) + ks * 32);
                const int i = q * 16;
                MMA16816(acc[i + 0], acc[i + 1], acc[i + 2], acc[i + 3],
                         a0, a1, a2, a3, b0, b1);
                MMA16816(acc[i + 4], acc[i + 5], acc[i + 6], acc[i + 7],
                         a4, a5, a6, a7, b0, b1);
                MMA16816(acc[i + 8], acc[i + 9], acc[i + 10], acc[i + 11],
                         a0, a1, a2, a3, b2, b3);
                MMA16816(acc[i + 12], acc[i + 13], acc[i + 14], acc[i + 15],
                         a4, a5, a6, a7, b2, b3);
            }
        }

        // ---- tanh + store h_new (this warp's 32 rows x 128 cols) ----
#pragma unroll
        for (int i = 0; i < 128; i++) acc[i] = tanh_fast(acc[i]);

        float* hp = h_out + (r0 + g) * 256 + nh * 128;
#pragma unroll
        for (int q = 0; q < 8; q++)
#pragma unroll
            for (int nt = 0; nt < 2; nt++) {
                const int i = q * 16 + nt * 8;
                const int n = q * 16 + nt * 8 + c0;
                *(float2*)(hp + n)             = make_float2(acc[i + 0], acc[i + 1]);
                *(float2*)(hp + 8 * 256 + n)   = make_float2(acc[i + 2], acc[i + 3]);
                *(float2*)(hp + 16 * 256 + n)  = make_float2(acc[i + 4], acc[i + 5]);
                *(float2*)(hp + 24 * 256 + n)  = make_float2(acc[i + 6], acc[i + 7]);
            }

        // ---- proj partials: 32 rows x 16 cols over this half's K=128 (A from acc regs) ----
        float pa[16];
#pragma unroll
        for (int i = 0; i < 16; i++) pa[i] = 0.0f;
#pragma unroll
        for (int pk = 0; pk < 8; pk++) {
            const int i = pk * 16;
            const uint32_t a0 = pack2(acc[i + 0],  acc[i + 1]);
            const uint32_t a1 = pack2(acc[i + 2],  acc[i + 3]);
            const uint32_t a2 = pack2(acc[i + 8],  acc[i + 9]);
            const uint32_t a3 = pack2(acc[i + 10], acc[i + 11]);
            const uint32_t a4 = pack2(acc[i + 4],  acc[i + 5]);
            const uint32_t a5 = pack2(acc[i + 6],  acc[i + 7]);
            const uint32_t a6 = pack2(acc[i + 12], acc[i + 13]);
            const uint32_t a7 = pack2(acc[i + 14], acc[i + 15]);
            uint32_t b00, b01, b10, b11;
            lds32(b00, pb0 + pk * 32); lds32(b01, pb0 + pk * 32 + 16);
            lds32(b10, pb1 + pk * 32); lds32(b11, pb1 + pk * 32 + 16);
            MMA16816(pa[0],  pa[1],  pa[2],  pa[3],  a0, a1, a2, a3, b00, b01);
            MMA16816(pa[4],  pa[5],  pa[6],  pa[7],  a4, a5, a6, a7, b00, b01);
            MMA16816(pa[8],  pa[9],  pa[10], pa[11], a0, a1, a2, a3, b10, b11);
            MMA16816(pa[12], pa[13], pa[14], pa[15], a4, a5, a6, a7, b10, b11);
        }

        // ---- exchange partials with pair partner via SMEM scratch ----
#pragma unroll
        for (int nt = 0; nt < 2; nt++)
#pragma unroll
            for (int half = 0; half < 2; half++) {
                const int i = nt * 8 + half * 4;
                const uint32_t base = scrW + (uint32_t)((g + half * 16) * 72 + (nt * 8 + c0) * 4);
                stsf2(base,           pa[i + 0], pa[i + 1]);            // row g(+16)
                stsf2(base + 8 * 72,  pa[i + 2], pa[i + 3]);            // row g+8(+24)
            }
        BAR_PAIR(barid);

        // my softmax rows: rA = g + nh*16, rB = rA + 8 (pa at half == nh)
        float l0[4], l1[4];
        {
            const uint32_t rdA = scrR + (uint32_t)((g + nh * 16) * 72);
            const uint32_t rdB = rdA + 8 * 72;
            float p0, p1;
            ldsf2(p0, p1, rdA + c0 * 4);
            l0[0] = pa[nh * 4 + 0] + p0 + sbproj[c0];
            l0[1] = pa[nh * 4 + 1] + p1 + sbproj[c0 + 1];
            ldsf2(p0, p1, rdB + c0 * 4);
            l1[0] = pa[nh * 4 + 2] + p0 + sbproj[c0];
            l1[1] = pa[nh * 4 + 3] + p1 + sbproj[c0 + 1];
            ldsf2(p0, p1, rdA + (8 + c0) * 4);
            l0[2] = pa[8 + nh * 4 + 0] + p0 + sbproj[8 + c0];
            l0[3] = pa[8 + nh * 4 + 1] + p1 + sbproj[9 + c0];
            ldsf2(p0, p1, rdB + (8 + c0) * 4);
            l1[2] = pa[8 + nh * 4 + 2] + p0 + sbproj[8 + c0];
            l1[3] = pa[8 + nh * 4 + 3] + p1 + sbproj[9 + c0];
        }
        BAR_PAIR(barid);   // reads done before next iteration's writes

        {
            const bool v1 = (8 + c0) < 12;
            if (!v1) { l0[2] = l0[3] = l1[2] = l1[3] = -1e30f; }

            float mx0 = fmaxf(fmaxf(l0[0], l0[1]), fmaxf(l0[2], l0[3]));
            float mx1 = fmaxf(fmaxf(l1[0], l1[1]), fmaxf(l1[2], l1[3]));
            mx0 = fmaxf(mx0, __shfl_xor_sync(0xFFFFFFFFu, mx0, 1));
            mx0 = fmaxf(mx0, __shfl_xor_sync(0xFFFFFFFFu, mx0, 2));
            mx1 = fmaxf(mx1, __shfl_xor_sync(0xFFFFFFFFu, mx1, 1));
            mx1 = fmaxf(mx1, __shfl_xor_sync(0xFFFFFFFFu, mx1, 2));

            float s0 = 0.f, s1 = 0.f;
#pragma unroll
            for (int j = 0; j < 4; j++) { l0[j] = __expf(l0[j] - mx0); s0 += l0[j]; }
#pragma unroll
            for (int j = 0; j < 4; j++) { l1[j] = __expf(l1[j] - mx1); s1 += l1[j]; }
            s0 += __shfl_xor_sync(0xFFFFFFFFu, s0, 1);
            s0 += __shfl_xor_sync(0xFFFFFFFFu, s0, 2);
            s1 += __shfl_xor_sync(0xFFFFFFFFu, s1, 1);
            s1 += __shfl_xor_sync(0xFFFFFFFFu, s1, 2);
            const float i0 = __fdividef(1.0f, s0);
            const float i1 = __fdividef(1.0f, s1);

            float* o0 = out + (r0 + g + nh * 16) * 12;
            float* o1 = o0 + 8 * 12;
            *(float2*)(o0 + c0) = make_float2(l0[0] * i0, l0[1] * i0);
            *(float2*)(o1 + c0) = make_float2(l1[0] * i1, l1[1] * i1);
            if (v1) {
                *(float2*)(o0 + 8 + c0) = make_float2(l0[2] * i0, l0[3] * i0);
                *(float2*)(o1 + 8 + c0) = make_float2(l1[2] * i1, l1[3] * i1);
            }
        }
    }
}

extern "C" void kernel_launch(void* const* d_in, const int* in_sizes, int n_in,
                              void* d_out, int out_size) {
    const float* x      = (const float*)d_in[0];
    const float* hidden = (const float*)d_in[1];
    const float* W_ih   = (const float*)d_in[2];
    const float* b_ih   = (const float*)d_in[3];
    const float* W_hh   = (const float*)d_in[4];
    const float* b_hh   = (const float*)d_in[5];
    const float* W_proj = (const float*)d_in[6];
    const float* b_proj = (const float*)d_in[7];

    const int N = in_sizes[0] / 24;            // 524288
    float* out   = (float*)d_out;              // [N,12] softmax
    float* h_out = out + (size_t)N * 12;       // [N,256] h_new

    cudaFuncSetAttribute(rnn_kernel, cudaFuncAttributeMaxDynamicSharedMemorySize, SM_TOTAL);

    prep_kernel<<<329, 256>>>(W_ih, W_hh, W_proj);               // 84224 threads exactly
    rnn_kernel<<<152, 256, SM_TOTAL>>>(x, hidden, b_ih, b_hh, b_proj,
                                       out, h_out, N / 32);      // persistent; tiles of 32 rows
}